// round 3
// baseline (speedup 1.0000x reference)
#include <cuda_runtime.h>
#include <math.h>

#define H 2048
#define S 2048
#define V 50257

// ---------------- device scratch (allocation-free rule) ----------------
__device__ float g_part[32 * H];   // partial column sums of encoder_outputs
__device__ float g_cat[2 * H];     // [embedded ; attn_applied]
__device__ float g_x[H];           // relu(comb output)
__device__ float g_h[H];           // h_new
__device__ float g_logits[V];
__device__ float g_shift;          // max + log(sum exp(l - max))

__device__ __forceinline__ float warp_sum(float v) {
    #pragma unroll
    for (int o = 16; o > 0; o >>= 1) v += __shfl_xor_sync(0xffffffffu, v, o);
    return v;
}

// K1a: partial column sums of encoder_outputs. grid (8, 32) x 256 threads.
// block (bx,by): columns [bx*256, bx*256+256), rows [by*64, by*64+64)
__global__ void k1a_colsum_part(const float* __restrict__ enc) {
    int col = blockIdx.x * 256 + threadIdx.x;
    int r0  = blockIdx.y * 64;
    float s = 0.f;
    #pragma unroll 8
    for (int i = 0; i < 64; ++i)
        s += enc[(size_t)(r0 + i) * H + col];
    g_part[blockIdx.y * H + col] = s;
}

// K1b: finish column sums -> g_cat[H..2H), and gather embedding row -> g_cat[0..H)
__global__ void k1b_finish_cat(const float* __restrict__ emb,
                               const int* __restrict__ input_id) {
    int j = blockIdx.x * 256 + threadIdx.x;  // 8 blocks x 256 = 2048
    float s = 0.f;
    #pragma unroll
    for (int c = 0; c < 32; ++c) s += g_part[c * H + j];
    g_cat[H + j] = s;
    g_cat[j] = emb[(size_t)input_id[0] * H + j];
}

// K2: x = relu(comb_w @ cat + comb_b). warp-per-row. 256 blocks x 256 thr.
__global__ void k2_comb(const float* __restrict__ w, const float* __restrict__ b) {
    int warp = threadIdx.x >> 5, lane = threadIdx.x & 31;
    int row = blockIdx.x * 8 + warp;             // 2048 rows
    const float4* wr = (const float4*)(w + (size_t)row * 2 * H);
    const float4* cv = (const float4*)g_cat;
    float acc = 0.f;
    #pragma unroll 8
    for (int i = lane; i < (2 * H) / 4; i += 32) {
        float4 a = wr[i], x = cv[i];
        acc += a.x * x.x + a.y * x.y + a.z * x.z + a.w * x.w;
    }
    acc = warp_sum(acc);
    if (lane == 0) g_x[row] = fmaxf(acc + b[row], 0.f);
}

// K3: fused GRU step. warp-per-output-j computes all 6 dot products + gates.
// 256 blocks x 256 threads.
__global__ void k3_gru(const float* __restrict__ w_ih, const float* __restrict__ w_hh,
                       const float* __restrict__ b_ih, const float* __restrict__ b_hh,
                       const float* __restrict__ hprev) {
    int warp = threadIdx.x >> 5, lane = threadIdx.x & 31;
    int j = blockIdx.x * 8 + warp;               // 2048 outputs
    const float4* xr = (const float4*)(w_ih + (size_t)j * H);
    const float4* xz = (const float4*)(w_ih + (size_t)(H + j) * H);
    const float4* xn = (const float4*)(w_ih + (size_t)(2 * H + j) * H);
    const float4* hr = (const float4*)(w_hh + (size_t)j * H);
    const float4* hz = (const float4*)(w_hh + (size_t)(H + j) * H);
    const float4* hn = (const float4*)(w_hh + (size_t)(2 * H + j) * H);
    const float4* xv = (const float4*)g_x;
    const float4* hv = (const float4*)hprev;

    float sr = 0.f, sz = 0.f, sxn = 0.f, shn = 0.f;
    #pragma unroll 4
    for (int i = lane; i < H / 4; i += 32) {
        float4 x = xv[i], h = hv[i];
        float4 a;
        a = xr[i]; sr  += a.x * x.x + a.y * x.y + a.z * x.z + a.w * x.w;
        a = hr[i]; sr  += a.x * h.x + a.y * h.y + a.z * h.z + a.w * h.w;
        a = xz[i]; sz  += a.x * x.x + a.y * x.y + a.z * x.z + a.w * x.w;
        a = hz[i]; sz  += a.x * h.x + a.y * h.y + a.z * h.z + a.w * h.w;
        a = xn[i]; sxn += a.x * x.x + a.y * x.y + a.z * x.z + a.w * x.w;
        a = hn[i]; shn += a.x * h.x + a.y * h.y + a.z * h.z + a.w * h.w;
    }
    sr = warp_sum(sr); sz = warp_sum(sz);
    sxn = warp_sum(sxn); shn = warp_sum(shn);
    if (lane == 0) {
        float pre_r = sr + b_ih[j] + b_hh[j];
        float pre_z = sz + b_ih[H + j] + b_hh[H + j];
        float r = 1.f / (1.f + expf(-pre_r));
        float z = 1.f / (1.f + expf(-pre_z));
        float n = tanhf(sxn + b_ih[2 * H + j] + r * (shn + b_hh[2 * H + j]));
        float hp = hprev[j];
        g_h[j] = (1.f - z) * n + z * hp;
    }
}

// K4a: logits = out_w @ h_new + out_b. warp-per-row. 6283 blocks x 256 thr.
__global__ void k4a_out(const float* __restrict__ w, const float* __restrict__ b) {
    int warp = threadIdx.x >> 5, lane = threadIdx.x & 31;
    int row = blockIdx.x * 8 + warp;
    if (row >= V) return;
    const float4* wr = (const float4*)(w + (size_t)row * H);
    const float4* hv = (const float4*)g_h;
    float acc = 0.f;
    #pragma unroll 16
    for (int i = lane; i < H / 4; i += 32) {
        float4 a = wr[i], h = hv[i];
        acc += a.x * h.x + a.y * h.y + a.z * h.z + a.w * h.w;
    }
    acc = warp_sum(acc);
    if (lane == 0) g_logits[row] = acc + b[row];
}

// K4b: single-block online logsumexp over g_logits -> g_shift.
__global__ void k4b_lse() {
    __shared__ float sm[1024], ss[1024];
    int tid = threadIdx.x;
    float m = -INFINITY, s = 0.f;
    for (int i = tid; i < V; i += 1024) {
        float l = g_logits[i];
        float nm = fmaxf(m, l);
        s = s * expf(m - nm) + expf(l - nm);
        m = nm;
    }
    sm[tid] = m; ss[tid] = s;
    __syncthreads();
    for (int o = 512; o > 0; o >>= 1) {
        if (tid < o) {
            float m2 = sm[tid + o], s2 = ss[tid + o];
            float nm = fmaxf(sm[tid], m2);
            ss[tid] = ss[tid] * expf(sm[tid] - nm) + s2 * expf(m2 - nm);
            sm[tid] = nm;
        }
        __syncthreads();
    }
    if (tid == 0) g_shift = sm[0] + logf(ss[0]);
}

// K4c: write all outputs: log_probs (V) | h_new (H) | attn_weights=1 (S)
__global__ void k4c_write(float* __restrict__ out, int out_size) {
    int i = blockIdx.x * 256 + threadIdx.x;
    if (i >= out_size) return;
    if (i < V)            out[i] = g_logits[i] - g_shift;
    else if (i < V + H)   out[i] = g_h[i - V];
    else                  out[i] = 1.0f;
}

extern "C" void kernel_launch(void* const* d_in, const int* in_sizes, int n_in,
                              void* d_out, int out_size) {
    const int*   input_id = (const int*)  d_in[0];
    const float* hidden   = (const float*)d_in[1];   // (1,1,H)
    const float* enc      = (const float*)d_in[2];   // (S,H)
    const float* emb      = (const float*)d_in[3];   // (V,H)
    // d_in[4], d_in[5]: attn_w / attn_b — provably unused (softmax over singleton)
    const float* comb_w   = (const float*)d_in[6];
    const float* comb_b   = (const float*)d_in[7];
    const float* w_ih     = (const float*)d_in[8];
    const float* w_hh     = (const float*)d_in[9];
    const float* b_ih     = (const float*)d_in[10];
    const float* b_hh     = (const float*)d_in[11];
    const float* out_w    = (const float*)d_in[12];
    const float* out_b    = (const float*)d_in[13];
    float* out = (float*)d_out;

    k1a_colsum_part<<<dim3(H / 256, 32), 256>>>(enc);
    k1b_finish_cat<<<H / 256, 256>>>(emb, input_id);
    k2_comb<<<H / 8, 256>>>(comb_w, comb_b);
    k3_gru<<<H / 8, 256>>>(w_ih, w_hh, b_ih, b_hh, hidden);
    k4a_out<<<(V + 7) / 8, 256>>>(out_w, out_b);
    k4b_lse<<<1, 1024>>>();
    k4c_write<<<(out_size + 255) / 256, 256>>>(out, out_size);
}

// round 4
// speedup vs baseline: 1.0535x; 1.0535x over previous
#include <cuda_runtime.h>
#include <math.h>

#define H 2048
#define S 2048
#define V 50257

// ---------------- device scratch (allocation-free rule) ----------------
__device__ float g_part[64 * H];   // partial column sums of encoder_outputs
__device__ float g_cat[2 * H];     // [embedded ; attn_applied]
__device__ float g_x[H];           // relu(comb output)
__device__ float g_gh[3 * H];      // w_hh @ h0 dots
__device__ float g_gx[3 * H];      // w_ih @ x dots
__device__ float g_h[H];           // h_new
__device__ float g_logits[V];
__device__ float g_shift;          // max + log(sum exp(l - max))

__device__ __forceinline__ float warp_sum(float v) {
    #pragma unroll
    for (int o = 16; o > 0; o >>= 1) v += __shfl_xor_sync(0xffffffffu, v, o);
    return v;
}

__device__ __forceinline__ float dot_row_warp(const float4* __restrict__ wr,
                                              const float4* __restrict__ xv,
                                              int n4, int lane) {
    float acc = 0.f;
    #pragma unroll 16
    for (int i = lane; i < n4; i += 32) {
        float4 a = wr[i], x = xv[i];
        acc += a.x * x.x + a.y * x.y + a.z * x.z + a.w * x.w;
    }
    return warp_sum(acc);
}

// K1: fused independent work, partitioned by blockIdx.x (1288 blocks x 256 thr):
//   [0, 768)       : gh = w_hh @ h0, warp-per-row (6144 rows)
//   [768, 1280)    : enc column-sum partials (8 col-chunks x 64 row-chunks of 32)
//   [1280, 1288)   : embedding gather -> g_cat[0..H)
__global__ void k1_fused(const float* __restrict__ w_hh,
                         const float* __restrict__ hprev,
                         const float* __restrict__ enc,
                         const float* __restrict__ emb,
                         const int* __restrict__ input_id) {
    int b = blockIdx.x;
    if (b < 768) {
        int warp = threadIdx.x >> 5, lane = threadIdx.x & 31;
        int row = b * 8 + warp;                      // 0..6143
        float d = dot_row_warp((const float4*)(w_hh + (size_t)row * H),
                               (const float4*)hprev, H / 4, lane);
        if (lane == 0) g_gh[row] = d;
    } else if (b < 1280) {
        int cb = b - 768;
        int col = (cb & 7) * 256 + threadIdx.x;
        int rc  = cb >> 3;                           // 0..63
        int r0  = rc * 32;
        float s = 0.f;
        #pragma unroll
        for (int i = 0; i < 32; ++i)
            s += enc[(size_t)(r0 + i) * H + col];
        g_part[rc * H + col] = s;
    } else {
        int j = (b - 1280) * 256 + threadIdx.x;      // 0..2047
        g_cat[j] = emb[(size_t)input_id[0] * H + j];
    }
}

// K2: finish column sums -> g_cat[H..2H)
__global__ void k2_finish_cat() {
    int j = blockIdx.x * 256 + threadIdx.x;
    float s = 0.f;
    #pragma unroll
    for (int c = 0; c < 64; ++c) s += g_part[c * H + j];
    g_cat[H + j] = s;
}

// K3: x = relu(comb_w @ cat + comb_b). warp-per-row, full-unroll 32.
__global__ void k3_comb(const float* __restrict__ w, const float* __restrict__ b) {
    int warp = threadIdx.x >> 5, lane = threadIdx.x & 31;
    int row = blockIdx.x * 8 + warp;                 // 2048 rows
    const float4* wr = (const float4*)(w + (size_t)row * 2 * H);
    const float4* cv = (const float4*)g_cat;
    float acc = 0.f;
    #pragma unroll
    for (int i = lane; i < (2 * H) / 4; i += 32) {
        float4 a = wr[i], x = cv[i];
        acc += a.x * x.x + a.y * x.y + a.z * x.z + a.w * x.w;
    }
    acc = warp_sum(acc);
    if (lane == 0) g_x[row] = fmaxf(acc + b[row], 0.f);
}

// K4: gx = w_ih @ x. warp-per-row (6144 rows), 768 blocks.
__global__ void k4_wih(const float* __restrict__ w_ih) {
    int warp = threadIdx.x >> 5, lane = threadIdx.x & 31;
    int row = blockIdx.x * 8 + warp;
    float d = dot_row_warp((const float4*)(w_ih + (size_t)row * H),
                           (const float4*)g_x, H / 4, lane);
    if (lane == 0) g_gx[row] = d;
}

// K5: elementwise GRU gates -> g_h. 8 blocks x 256.
__global__ void k5_gates(const float* __restrict__ b_ih, const float* __restrict__ b_hh,
                         const float* __restrict__ hprev) {
    int j = blockIdx.x * 256 + threadIdx.x;
    float pre_r = g_gx[j]         + b_ih[j]         + g_gh[j]         + b_hh[j];
    float pre_z = g_gx[H + j]     + b_ih[H + j]     + g_gh[H + j]     + b_hh[H + j];
    float r = 1.f / (1.f + expf(-pre_r));
    float z = 1.f / (1.f + expf(-pre_z));
    float n = tanhf(g_gx[2 * H + j] + b_ih[2 * H + j]
                    + r * (g_gh[2 * H + j] + b_hh[2 * H + j]));
    g_h[j] = (1.f - z) * n + z * hprev[j];
}

// K6: logits = out_w @ h_new + out_b. warp-per-row (50257 rows).
__global__ void k6_out(const float* __restrict__ w, const float* __restrict__ b) {
    int warp = threadIdx.x >> 5, lane = threadIdx.x & 31;
    int row = blockIdx.x * 8 + warp;
    if (row >= V) return;
    float d = dot_row_warp((const float4*)(w + (size_t)row * H),
                           (const float4*)g_h, H / 4, lane);
    if (lane == 0) g_logits[row] = d + b[row];
}

// K7: single-block online logsumexp over g_logits -> g_shift.
__global__ void k7_lse() {
    __shared__ float sm[1024], ss[1024];
    int tid = threadIdx.x;
    float m = -INFINITY, s = 0.f;
    for (int i = tid; i < V; i += 1024) {
        float l = g_logits[i];
        float nm = fmaxf(m, l);
        s = s * expf(m - nm) + expf(l - nm);
        m = nm;
    }
    sm[tid] = m; ss[tid] = s;
    __syncthreads();
    for (int o = 512; o > 0; o >>= 1) {
        if (tid < o) {
            float m2 = sm[tid + o], s2 = ss[tid + o];
            float nm = fmaxf(sm[tid], m2);
            ss[tid] = ss[tid] * expf(sm[tid] - nm) + s2 * expf(m2 - nm);
            sm[tid] = nm;
        }
        __syncthreads();
    }
    if (tid == 0) g_shift = sm[0] + logf(ss[0]);
}

// K8: write outputs: log_probs (V) | h_new (H) | attn_weights=1 (S)
__global__ void k8_write(float* __restrict__ out, int out_size) {
    int i = blockIdx.x * 256 + threadIdx.x;
    if (i >= out_size) return;
    if (i < V)            out[i] = g_logits[i] - g_shift;
    else if (i < V + H)   out[i] = g_h[i - V];
    else                  out[i] = 1.0f;
}

extern "C" void kernel_launch(void* const* d_in, const int* in_sizes, int n_in,
                              void* d_out, int out_size) {
    const int*   input_id = (const int*)  d_in[0];
    const float* hidden   = (const float*)d_in[1];   // (1,1,H)
    const float* enc      = (const float*)d_in[2];   // (S,H)
    const float* emb      = (const float*)d_in[3];   // (V,H)
    // d_in[4], d_in[5]: attn_w / attn_b — provably dead (softmax over singleton)
    const float* comb_w   = (const float*)d_in[6];
    const float* comb_b   = (const float*)d_in[7];
    const float* w_ih     = (const float*)d_in[8];
    const float* w_hh     = (const float*)d_in[9];
    const float* b_ih     = (const float*)d_in[10];
    const float* b_hh     = (const float*)d_in[11];
    const float* out_w    = (const float*)d_in[12];
    const float* out_b    = (const float*)d_in[13];
    float* out = (float*)d_out;

    k1_fused<<<1288, 256>>>(w_hh, hidden, enc, emb, input_id);
    k2_finish_cat<<<H / 256, 256>>>();
    k3_comb<<<H / 8, 256>>>(comb_w, comb_b);
    k4_wih<<<768, 256>>>(w_ih);
    k5_gates<<<H / 256, 256>>>(b_ih, b_hh, hidden);
    k6_out<<<(V + 7) / 8, 256>>>(out_w, out_b);
    k7_lse<<<1, 1024>>>();
    k8_write<<<(out_size + 255) / 256, 256>>>(out, out_size);
}